// round 15
// baseline (speedup 1.0000x reference)
#include <cuda_runtime.h>
#include <cuda_bf16.h>
#include <math.h>

#define NROWS 65536
#define DIM   256
#define KCB   1024

#define OFF_LOSS 0
#define OFF_Q    1
#define OFF_PERP (1 + NROWS*DIM)
#define OFF_EMB  (OFF_PERP + 1)
#define OFF_CS   (OFF_EMB + KCB*DIM)
#define OFF_EMA  (OFF_CS + KCB)

__device__ float  g_A[NROWS];
__device__ float  g_C[KCB];
__device__ int    g_idx[NROWS];
__device__ int    g_cand[NROWS*3];
__device__ float  g_cd[NROWS*3];
__device__ float  g_counts[KCB];
__device__ float  g_dw[KCB*DIM];
__device__ float  g_cs[KCB];
__device__ double g_lp[2048];
__device__ int    g_ccount[KCB];
__device__ int    g_cursor[KCB];
__device__ int    g_off[KCB];
__device__ int    g_rows[NROWS];

__device__ __align__(16) __nv_bfloat16 g_xb[NROWS*DIM];
__device__ __align__(16) __nv_bfloat16 g_wb[KCB*DIM];

__device__ __forceinline__ unsigned smem_u32(const void* p) {
    unsigned a;
    asm("{ .reg .u64 t; cvta.to.shared.u64 t, %1; cvt.u32.u64 %0, t; }" : "=r"(a) : "l"(p));
    return a;
}
__device__ __forceinline__ int dless(float da, int ia, float db, int ib) {
    return (da < db) || (da == db && ia < ib);
}
#define CP_ASYNC16(dst, src) asm volatile("cp.async.cg.shared.global [%0], [%1], 16;" :: "r"(dst), "l"(src) : "memory")
#define CP_COMMIT()          asm volatile("cp.async.commit_group;" ::: "memory")
#define CP_WAIT(n)           asm volatile("cp.async.wait_group %0;" :: "n"(n) : "memory")
#define LDSM4(r0,r1,r2,r3,addr) \
    asm volatile("ldmatrix.sync.aligned.m8n8.x4.shared.b16 {%0,%1,%2,%3}, [%4];" \
        : "=r"(r0),"=r"(r1),"=r"(r2),"=r"(r3) : "r"(addr))

__device__ __forceinline__ void mma16816(float* c, const unsigned* a, unsigned b0, unsigned b1) {
    asm volatile("mma.sync.aligned.m16n8k16.row.col.f32.bf16.bf16.f32 "
        "{%0,%1,%2,%3}, {%4,%5,%6,%7}, {%8,%9}, {%0,%1,%2,%3};"
        : "+f"(c[0]), "+f"(c[1]), "+f"(c[2]), "+f"(c[3])
        : "r"(a[0]), "r"(a[1]), "r"(a[2]), "r"(a[3]), "r"(b0), "r"(b1));
}

// ---------------- fused cast + rownorm ----------------
__global__ __launch_bounds__(256) void k_prep(const float* __restrict__ src, int nrows,
                                              int which, __nv_bfloat16* __restrict__ dst) {
    int wd = threadIdx.x >> 5, l = threadIdx.x & 31;
    int row = blockIdx.x * 8 + wd;
    if (row >= nrows) return;
    const float4* r4 = (const float4*)(src + (size_t)row * DIM);
    float4 a = r4[l], b = r4[l + 32];
    ushort4 ua, ub;
    ua.x = __bfloat16_as_ushort(__float2bfloat16_rn(a.x));
    ua.y = __bfloat16_as_ushort(__float2bfloat16_rn(a.y));
    ua.z = __bfloat16_as_ushort(__float2bfloat16_rn(a.z));
    ua.w = __bfloat16_as_ushort(__float2bfloat16_rn(a.w));
    ub.x = __bfloat16_as_ushort(__float2bfloat16_rn(b.x));
    ub.y = __bfloat16_as_ushort(__float2bfloat16_rn(b.y));
    ub.z = __bfloat16_as_ushort(__float2bfloat16_rn(b.z));
    ub.w = __bfloat16_as_ushort(__float2bfloat16_rn(b.w));
    ushort4* d4 = (ushort4*)(dst + (size_t)row * DIM);
    d4[l] = ua; d4[l + 32] = ub;
    double s = (double)a.x*a.x + (double)a.y*a.y + (double)a.z*a.z + (double)a.w*a.w
             + (double)b.x*b.x + (double)b.y*b.y + (double)b.z*b.z + (double)b.w*b.w;
#pragma unroll
    for (int o = 16; o; o >>= 1) s += __shfl_down_sync(0xffffffffu, s, o);
    if (!l) { if (which) g_C[row] = (float)s; else g_A[row] = (float)s; }
}

// ---- bucket zero (occupies ncu slot 3 so k_mma_cand lands in slot 4) ----
__global__ __launch_bounds__(256) void k_zero() {
    int i = blockIdx.x * 256 + threadIdx.x;
    if (i < KCB) { g_ccount[i] = 0; g_cursor[i] = 0; }
}

// ---------------- raw-MMA distance GEMM -> global top-3 candidates ----------------
// B streamed in 64-k chunks (half the barriers of the 32-k version)
#define LDA 264
#define LDB 72
#define AS_BYTES (128*LDA*2)
#define BS_BYTES (128*LDB*2)
#define OFF_AS   0
#define OFF_BS   (AS_BYTES)
#define OFF_SC   (OFF_BS + 2*BS_BYTES)
#define OFF_MG   (OFF_SC + 4096)
#define SMEM_TOT (OFF_MG + 128*2*3*8)

__device__ __forceinline__ void prefetch_b(char* smem, int tid, int buf, int kch, int ct) {
    int code = tid >> 1, half = tid & 1;
    const __nv_bfloat16* src = g_wb + (size_t)(ct + code) * DIM + kch * 64 + half * 32;
    unsigned dst = smem_u32(smem + OFF_BS + buf * BS_BYTES + (code * LDB + half * 32) * 2);
    CP_ASYNC16(dst,      src);
    CP_ASYNC16(dst + 16, src + 8);
    CP_ASYNC16(dst + 32, src + 16);
    CP_ASYNC16(dst + 48, src + 24);
    CP_COMMIT();
}

__global__ __launch_bounds__(256,2) void k_mma_cand() {
    extern __shared__ char smem[];
    __nv_bfloat16* As = (__nv_bfloat16*)(smem + OFF_AS);
    float* sC = (float*)(smem + OFF_SC);
    int tid = threadIdx.x, w = tid >> 5, lane = tid & 31;
    int rowBase = blockIdx.x * 128;
    int rw = w >> 1, cw = w & 1;
    int ql = lane >> 2, qc = lane & 3;

    for (int i = tid; i < KCB; i += 256) sC[i] = g_C[i];
    for (int u = tid; u < 128 * 32; u += 256) {
        int r = u >> 5, c8 = u & 31;
        *(uint4*)(As + r * LDA + c8 * 8) =
            *(const uint4*)(g_xb + (size_t)(rowBase + r) * DIM + c8 * 8);
    }
    __syncthreads();

    unsigned asb = smem_u32(As);
    unsigned bsb = smem_u32(smem + OFF_BS);

    float Ar[4];
#pragma unroll
    for (int rs = 0; rs < 4; rs++)
        Ar[rs] = g_A[rowBase + rw * 32 + (rs >> 1) * 16 + (rs & 1) * 8 + ql];

    float tD[4][3]; int tI[4][3];
#pragma unroll
    for (int rs = 0; rs < 4; rs++)
#pragma unroll
        for (int s = 0; s < 3; s++) { tD[rs][s] = 3.4e38f; tI[rs][s] = 0x7ffffff0 + s; }

    int a_roff = ((lane >> 3) & 1) * 8 + (lane & 7);
    int a_koff = (lane >> 4) * 8;
    int b_noff = (lane >> 4) * 8 + (lane & 7);
    int b_koff = ((lane >> 3) & 1) * 8;

    // hoisted ldmatrix base addresses (k-independent parts)
    unsigned a_base[2];
#pragma unroll
    for (int mt = 0; mt < 2; mt++)
        a_base[mt] = asb + ((rw * 32 + mt * 16 + a_roff) * LDA + a_koff) * 2;
    unsigned b_base[4];
#pragma unroll
    for (int ng = 0; ng < 4; ng++)
        b_base[ng] = ((cw * 64 + ng * 16 + b_noff) * LDB + b_koff) * 2;

    for (int ct8 = 0; ct8 < 8; ct8++) {
        int ct = ct8 * 128;
        float acc[2][8][4];
#pragma unroll
        for (int mt = 0; mt < 2; mt++)
#pragma unroll
            for (int nt = 0; nt < 8; nt++)
#pragma unroll
                for (int v = 0; v < 4; v++) acc[mt][nt][v] = 0.f;

        prefetch_b(smem, tid, 0, 0, ct);
        for (int kch = 0; kch < 4; kch++) {
            if (kch + 1 < 4) { prefetch_b(smem, tid, (kch + 1) & 1, kch + 1, ct); CP_WAIT(1); }
            else             { CP_WAIT(0); }
            __syncthreads();
            unsigned bb = bsb + (kch & 1) * BS_BYTES;
#pragma unroll
            for (int ks = 0; ks < 4; ks++) {
                int kcol = kch * 64 + ks * 16;
                int bkcol = ks * 16;
                unsigned a[2][4];
#pragma unroll
                for (int mt = 0; mt < 2; mt++)
                    LDSM4(a[mt][0], a[mt][1], a[mt][2], a[mt][3], a_base[mt] + kcol * 2);
#pragma unroll
                for (int ng = 0; ng < 4; ng++) {
                    unsigned b0, b1, b2, b3;
                    LDSM4(b0, b1, b2, b3, bb + b_base[ng] + bkcol * 2);
#pragma unroll
                    for (int mt = 0; mt < 2; mt++) {
                        mma16816(acc[mt][2 * ng],     a[mt], b0, b1);
                        mma16816(acc[mt][2 * ng + 1], a[mt], b2, b3);
                    }
                }
            }
            __syncthreads();
        }

        // register epilogue: distances + threshold-filtered top-3
#pragma unroll
        for (int mt = 0; mt < 2; mt++)
#pragma unroll
            for (int nt = 0; nt < 8; nt++) {
                int cb = ct + cw * 64 + nt * 8 + qc * 2;
#pragma unroll
                for (int v = 0; v < 4; v++) {
                    int rs = mt * 2 + (v >> 1);
                    int code = cb + (v & 1);
                    float d = __fadd_rn(__fsub_rn(Ar[rs], __fmul_rn(2.0f, acc[mt][nt][v])),
                                        sC[code]);
                    if (d < tD[rs][2]) {
                        if (d < tD[rs][0]) {
                            tD[rs][2] = tD[rs][1]; tI[rs][2] = tI[rs][1];
                            tD[rs][1] = tD[rs][0]; tI[rs][1] = tI[rs][0];
                            tD[rs][0] = d; tI[rs][0] = code;
                        } else if (d < tD[rs][1]) {
                            tD[rs][2] = tD[rs][1]; tI[rs][2] = tI[rs][1];
                            tD[rs][1] = d; tI[rs][1] = code;
                        } else {
                            tD[rs][2] = d; tI[rs][2] = code;
                        }
                    }
                }
            }
    }

    // merge the 4 lanes (qc 0..3) sharing each row
#pragma unroll
    for (int rs = 0; rs < 4; rs++) {
#pragma unroll
        for (int step = 1; step <= 2; step++) {
            float md[6]; int mi[6];
#pragma unroll
            for (int s = 0; s < 3; s++) {
                md[s] = tD[rs][s]; mi[s] = tI[rs][s];
                md[3 + s] = __shfl_xor_sync(0xffffffffu, tD[rs][s], step);
                mi[3 + s] = __shfl_xor_sync(0xffffffffu, tI[rs][s], step);
            }
#pragma unroll
            for (int p = 0; p < 3; p++)
#pragma unroll
                for (int q = p + 1; q < 6; q++)
                    if (dless(md[q], mi[q], md[p], mi[p])) {
                        float td = md[p]; md[p] = md[q]; md[q] = td;
                        int   ti = mi[p]; mi[p] = mi[q]; mi[q] = ti;
                    }
#pragma unroll
            for (int s = 0; s < 3; s++) { tD[rs][s] = md[s]; tI[rs][s] = mi[s]; }
        }
    }

    float* mD = (float*)(smem + OFF_MG);
    int*   mI = (int*)(smem + OFF_MG + 128 * 2 * 3 * 4);
    if (qc == 0) {
#pragma unroll
        for (int rs = 0; rs < 4; rs++) {
            int rloc = rw * 32 + (rs >> 1) * 16 + (rs & 1) * 8 + ql;
#pragma unroll
            for (int s = 0; s < 3; s++) {
                mD[(rloc * 2 + cw) * 3 + s] = tD[rs][s];
                mI[(rloc * 2 + cw) * 3 + s] = tI[rs][s];
            }
        }
    }
    __syncthreads();
    if (tid < 128) {
        float md[6]; int mi[6];
#pragma unroll
        for (int s = 0; s < 3; s++) {
            md[s]     = mD[(tid * 2 + 0) * 3 + s]; mi[s]     = mI[(tid * 2 + 0) * 3 + s];
            md[3 + s] = mD[(tid * 2 + 1) * 3 + s]; mi[3 + s] = mI[(tid * 2 + 1) * 3 + s];
        }
#pragma unroll
        for (int p = 0; p < 3; p++)
#pragma unroll
            for (int q = p + 1; q < 6; q++)
                if (dless(md[q], mi[q], md[p], mi[p])) {
                    float td = md[p]; md[p] = md[q]; md[q] = td;
                    int   ti = mi[p]; mi[p] = mi[q]; mi[q] = ti;
                }
        int row = rowBase + tid;
#pragma unroll
        for (int s = 0; s < 3; s++) {
            g_cand[row * 3 + s] = mi[s];
            g_cd[row * 3 + s]   = md[s];
        }
    }
}

// ---------------- margin-gated exact rescore + fused histogram ----------------
#define MARGIN 1.5e-3f
__global__ __launch_bounds__(256) void k_rescore(const float* __restrict__ x,
                                                 const float* __restrict__ w) {
    int row = blockIdx.x * 256 + threadIdx.x;
    if (row >= NROWS) return;
    int c0 = g_cand[row * 3], c1 = g_cand[row * 3 + 1], c2 = g_cand[row * 3 + 2];
    float d0 = g_cd[row * 3], d1 = g_cd[row * 3 + 1];
    int bi;
    if (__fsub_rn(d1, d0) > MARGIN) {
        bi = c0;
    } else {
        int c[3] = { c0, c1, c2 };
        const float4* xr = (const float4*)(x + (size_t)row * DIM);
        const float4* wr[3];
#pragma unroll
        for (int s = 0; s < 3; s++) wr[s] = (const float4*)(w + (size_t)c[s] * DIM);
        float dot[3] = { 0.f, 0.f, 0.f };
#pragma unroll 4
        for (int k4 = 0; k4 < 64; k4++) {
            float4 xv = xr[k4];
#pragma unroll
            for (int s = 0; s < 3; s++) {
                float4 wv = wr[s][k4];
                dot[s] = __fmaf_rn(xv.x, wv.x, dot[s]);
                dot[s] = __fmaf_rn(xv.y, wv.y, dot[s]);
                dot[s] = __fmaf_rn(xv.z, wv.z, dot[s]);
                dot[s] = __fmaf_rn(xv.w, wv.w, dot[s]);
            }
        }
        float A = g_A[row];
        float bd = 3.4e38f; bi = 0x7fffffff;
#pragma unroll
        for (int s = 0; s < 3; s++) {
            float d = __fadd_rn(__fsub_rn(A, __fmul_rn(2.0f, dot[s])), g_C[c[s]]);
            if (dless(d, c[s], bd, bi)) { bd = d; bi = c[s]; }
        }
    }
    g_idx[row] = bi;
    atomicAdd(&g_ccount[bi], 1);
}

// ---- bucket pipeline: scan -> scatter -> dw gather ----
__global__ __launch_bounds__(1024) void k_scan() {
    __shared__ int sh[1024];
    int t = threadIdx.x;
    int v = g_ccount[t];
    sh[t] = v;
    __syncthreads();
    int sum = v;
    for (int o = 1; o < 1024; o <<= 1) {
        int add = (t >= o) ? sh[t - o] : 0;
        __syncthreads();
        sh[t] = sum = sum + add;
        __syncthreads();
    }
    g_off[t] = sum - v;
    g_counts[t] = (float)v;
}

__global__ __launch_bounds__(256) void k_scatter() {
    int i = blockIdx.x * 256 + threadIdx.x;
    if (i >= NROWS) return;
    int k = g_idx[i];
    int pos = atomicAdd(&g_cursor[k], 1);
    g_rows[g_off[k] + pos] = i;
}

__global__ __launch_bounds__(256) void k_dw(const float* __restrict__ x) {
    int k = blockIdx.x, d = threadIdx.x;
    int off = g_off[k], m = g_ccount[k];
    float a0 = 0.f, a1 = 0.f;
    int j = 0;
    for (; j + 1 < m; j += 2) {
        a0 += x[(size_t)g_rows[off + j] * DIM + d];
        a1 += x[(size_t)g_rows[off + j + 1] * DIM + d];
    }
    if (j < m) a0 += x[(size_t)g_rows[off + j] * DIM + d];
    g_dw[k * DIM + d] = a0 + a1;
}

// ---- gather codebook, STE output, loss partials (2x ILP) ----
__global__ __launch_bounds__(256) void k_quant(const float* __restrict__ x,
                                               const float* __restrict__ w,
                                               float* __restrict__ out) {
    __shared__ double sr[256];
    double ls = 0.0;
    const int half = NROWS * DIM / 8;
    int stride = gridDim.x * 256;
    for (int e4 = blockIdx.x * 256 + threadIdx.x; e4 < half; e4 += stride) {
        int eA = e4, eB = e4 + half;
        int rowA = eA >> 6, c4A = eA & 63;
        int rowB = eB >> 6, c4B = eB & 63;
        int kA = g_idx[rowA], kB = g_idx[rowB];
        float4 xA = ((const float4*)x)[eA];
        float4 xB = ((const float4*)x)[eB];
        float4 qA = ((const float4*)w)[kA * 64 + c4A];
        float4 qB = ((const float4*)w)[kB * 64 + c4B];
        float a0 = __fsub_rn(qA.x, xA.x), a1 = __fsub_rn(qA.y, xA.y);
        float a2 = __fsub_rn(qA.z, xA.z), a3 = __fsub_rn(qA.w, xA.w);
        float b0 = __fsub_rn(qB.x, xB.x), b1 = __fsub_rn(qB.y, xB.y);
        float b2 = __fsub_rn(qB.z, xB.z), b3 = __fsub_rn(qB.w, xB.w);
        float* oA = out + OFF_Q + (size_t)eA * 4;
        float* oB = out + OFF_Q + (size_t)eB * 4;
        oA[0] = __fadd_rn(xA.x, a0); oA[1] = __fadd_rn(xA.y, a1);
        oA[2] = __fadd_rn(xA.z, a2); oA[3] = __fadd_rn(xA.w, a3);
        oB[0] = __fadd_rn(xB.x, b0); oB[1] = __fadd_rn(xB.y, b1);
        oB[2] = __fadd_rn(xB.z, b2); oB[3] = __fadd_rn(xB.w, b3);
        float sA = __fmaf_rn(a0, a0, __fmaf_rn(a1, a1, __fmaf_rn(a2, a2, a3 * a3)));
        float sB = __fmaf_rn(b0, b0, __fmaf_rn(b1, b1, __fmaf_rn(b2, b2, b3 * b3)));
        ls += (double)sA + (double)sB;
    }
    sr[threadIdx.x] = ls;
    __syncthreads();
    for (int o = 128; o; o >>= 1) { if (threadIdx.x < o) sr[threadIdx.x] += sr[threadIdx.x + o]; __syncthreads(); }
    if (!threadIdx.x) g_lp[blockIdx.x] = sr[0];
}

// ---- scalars ----
__global__ __launch_bounds__(256) void k_scalars(const float* __restrict__ ecs,
                                                 float* __restrict__ out) {
    __shared__ double sd[256];
    int t = threadIdx.x;
    double s = 0;
    for (int i = t; i < 2048; i += 256) s += g_lp[i];
    sd[t] = s; __syncthreads();
    for (int o = 128; o; o >>= 1) { if (t < o) sd[t] += sd[t + o]; __syncthreads(); }
    double loss = 0.25 * sd[0] / ((double)NROWS * DIM);
    double ns = 0;
    for (int k = t; k < KCB; k += 256) {
        float ncs = __fadd_rn(__fmul_rn(0.99f, ecs[k]), __fmul_rn(0.01f, g_counts[k]));
        out[OFF_CS + k] = ncs;
        ns += ncs;
    }
    __syncthreads(); sd[t] = ns; __syncthreads();
    for (int o = 128; o; o >>= 1) { if (t < o) sd[t] += sd[t + o]; __syncthreads(); }
    float nf = (float)sd[0];
    float denom = __fadd_rn(nf, (float)(1024.0 * 1e-5));
    for (int k = t; k < KCB; k += 256) {
        float ncs = out[OFF_CS + k];
        g_cs[k] = __fmul_rn(__fdiv_rn(__fadd_rn(ncs, 1e-5f), denom), nf);
    }
    double ps = 0;
    for (int k = t; k < KCB; k += 256) {
        double p = (double)g_counts[k] / (double)NROWS;
        ps += p * log(p + 1e-10);
    }
    __syncthreads(); sd[t] = ps; __syncthreads();
    for (int o = 128; o; o >>= 1) { if (t < o) sd[t] += sd[t + o]; __syncthreads(); }
    if (!t) { out[OFF_LOSS] = (float)loss; out[OFF_PERP] = (float)exp(-sd[0]); }
}

// ---- EMA codebook update ----
__global__ __launch_bounds__(256) void k_emb(const float* __restrict__ emaw,
                                             float* __restrict__ out) {
    int e = blockIdx.x*256 + threadIdx.x;
    if (e >= KCB*DIM) return;
    int k = e >> 8;
    float ne = __fadd_rn(__fmul_rn(0.99f, emaw[e]), __fmul_rn(0.01f, g_dw[e]));
    out[OFF_EMA + e] = ne;
    out[OFF_EMB + e] = __fdiv_rn(ne, g_cs[k]);
}

extern "C" void kernel_launch(void* const* d_in, const int* in_sizes, int n_in,
                              void* d_out, int out_size) {
    const float* x    = (const float*)d_in[0];
    const float* w    = (const float*)d_in[1];
    const float* ecs  = (const float*)d_in[2];
    const float* emaw = (const float*)d_in[3];
    float* out = (float*)d_out;

    cudaFuncSetAttribute(k_mma_cand,
        cudaFuncAttributeMaxDynamicSharedMemorySize, SMEM_TOT);

    __nv_bfloat16 *xb, *wb;
    cudaGetSymbolAddress((void**)&xb, g_xb);
    cudaGetSymbolAddress((void**)&wb, g_wb);

    k_prep<<<NROWS/8, 256>>>(x, NROWS, 0, xb);       // 1
    k_prep<<<KCB/8,   256>>>(w, KCB,   1, wb);       // 2
    k_zero<<<4, 256>>>();                            // 3
    k_mma_cand<<<NROWS/128, 256, SMEM_TOT>>>();      // 4 <- profiled slot
    k_rescore<<<NROWS/256, 256>>>(x, w);             // 5
    k_scan<<<1, 1024>>>();                           // 6
    k_scatter<<<NROWS/256, 256>>>();                 // 7
    k_dw<<<KCB, 256>>>(x);                           // 8
    k_quant<<<2048, 256>>>(x, w, out);               // 9
    k_scalars<<<1, 256>>>(ecs, out);                 // 10
    k_emb<<<KCB*DIM/256, 256>>>(emaw, out);          // 11
}

// round 16
// speedup vs baseline: 1.0390x; 1.0390x over previous
#include <cuda_runtime.h>
#include <cuda_bf16.h>
#include <math.h>

#define NROWS 65536
#define DIM   256
#define KCB   1024

#define OFF_LOSS 0
#define OFF_Q    1
#define OFF_PERP (1 + NROWS*DIM)
#define OFF_EMB  (OFF_PERP + 1)
#define OFF_CS   (OFF_EMB + KCB*DIM)
#define OFF_EMA  (OFF_CS + KCB)

__device__ float  g_A[NROWS];
__device__ float  g_C[KCB];
__device__ int    g_idx[NROWS];
__device__ int    g_cand[NROWS*3];
__device__ float  g_cd[NROWS*3];
__device__ float  g_counts[KCB];
__device__ float  g_dw[KCB*DIM];
__device__ float  g_cs[KCB];
__device__ double g_lp[2048];
__device__ int    g_ccount[KCB];
__device__ int    g_cursor[KCB];
__device__ int    g_off[KCB];
__device__ int    g_rows[NROWS];

__device__ __align__(16) __nv_bfloat16 g_xb[NROWS*DIM];
__device__ __align__(16) __nv_bfloat16 g_wb[KCB*DIM];

__device__ __forceinline__ unsigned smem_u32(const void* p) {
    unsigned a;
    asm("{ .reg .u64 t; cvta.to.shared.u64 t, %1; cvt.u32.u64 %0, t; }" : "=r"(a) : "l"(p));
    return a;
}
__device__ __forceinline__ int dless(float da, int ia, float db, int ib) {
    return (da < db) || (da == db && ia < ib);
}
#define CP_ASYNC16(dst, src) asm volatile("cp.async.cg.shared.global [%0], [%1], 16;" :: "r"(dst), "l"(src) : "memory")
#define CP_COMMIT()          asm volatile("cp.async.commit_group;" ::: "memory")
#define CP_WAIT(n)           asm volatile("cp.async.wait_group %0;" :: "n"(n) : "memory")
#define LDSM4(r0,r1,r2,r3,addr) \
    asm volatile("ldmatrix.sync.aligned.m8n8.x4.shared.b16 {%0,%1,%2,%3}, [%4];" \
        : "=r"(r0),"=r"(r1),"=r"(r2),"=r"(r3) : "r"(addr))

__device__ __forceinline__ void mma16816(float* c, const unsigned* a, unsigned b0, unsigned b1) {
    asm volatile("mma.sync.aligned.m16n8k16.row.col.f32.bf16.bf16.f32 "
        "{%0,%1,%2,%3}, {%4,%5,%6,%7}, {%8,%9}, {%0,%1,%2,%3};"
        : "+f"(c[0]), "+f"(c[1]), "+f"(c[2]), "+f"(c[3])
        : "r"(a[0]), "r"(a[1]), "r"(a[2]), "r"(a[3]), "r"(b0), "r"(b1));
}

// ---------------- fused cast + rownorm ----------------
__global__ __launch_bounds__(256) void k_prep(const float* __restrict__ src, int nrows,
                                              int which, __nv_bfloat16* __restrict__ dst) {
    int wd = threadIdx.x >> 5, l = threadIdx.x & 31;
    int row = blockIdx.x * 8 + wd;
    if (row >= nrows) return;
    const float4* r4 = (const float4*)(src + (size_t)row * DIM);
    float4 a = r4[l], b = r4[l + 32];
    ushort4 ua, ub;
    ua.x = __bfloat16_as_ushort(__float2bfloat16_rn(a.x));
    ua.y = __bfloat16_as_ushort(__float2bfloat16_rn(a.y));
    ua.z = __bfloat16_as_ushort(__float2bfloat16_rn(a.z));
    ua.w = __bfloat16_as_ushort(__float2bfloat16_rn(a.w));
    ub.x = __bfloat16_as_ushort(__float2bfloat16_rn(b.x));
    ub.y = __bfloat16_as_ushort(__float2bfloat16_rn(b.y));
    ub.z = __bfloat16_as_ushort(__float2bfloat16_rn(b.z));
    ub.w = __bfloat16_as_ushort(__float2bfloat16_rn(b.w));
    ushort4* d4 = (ushort4*)(dst + (size_t)row * DIM);
    d4[l] = ua; d4[l + 32] = ub;
    double s = (double)a.x*a.x + (double)a.y*a.y + (double)a.z*a.z + (double)a.w*a.w
             + (double)b.x*b.x + (double)b.y*b.y + (double)b.z*b.z + (double)b.w*b.w;
#pragma unroll
    for (int o = 16; o; o >>= 1) s += __shfl_down_sync(0xffffffffu, s, o);
    if (!l) { if (which) g_C[row] = (float)s; else g_A[row] = (float)s; }
}

// ---- bucket zero (occupies ncu slot 3 so k_mma_cand lands in slot 4) ----
__global__ __launch_bounds__(256) void k_zero() {
    int i = blockIdx.x * 256 + threadIdx.x;
    if (i < KCB) { g_ccount[i] = 0; g_cursor[i] = 0; }
}

// ---------------- raw-MMA distance GEMM -> global top-3 candidates ----------------
// R13-exact inner loop (32-k chunks) + cross-tile chunk0 prefetch before epilogue
#define LDA 264
#define LDB 40
#define AS_BYTES (128*LDA*2)
#define BS_BYTES (128*LDB*2)
#define OFF_AS   0
#define OFF_BS   (AS_BYTES)
#define OFF_SC   (OFF_BS + 2*BS_BYTES)
#define OFF_MG   (OFF_SC + 4096)
#define SMEM_TOT (OFF_MG + 128*2*3*8)

__device__ __forceinline__ void prefetch_b(char* smem, int tid, int buf, int kc, int ct) {
    int code = tid >> 1, half = tid & 1;
    const __nv_bfloat16* src = g_wb + (size_t)(ct + code) * DIM + kc * 32 + half * 16;
    unsigned dst = smem_u32(smem + OFF_BS + buf * BS_BYTES + (code * LDB + half * 16) * 2);
    CP_ASYNC16(dst, src);
    CP_ASYNC16(dst + 16, src + 8);
    CP_COMMIT();
}

__global__ __launch_bounds__(256,2) void k_mma_cand() {
    extern __shared__ char smem[];
    __nv_bfloat16* As = (__nv_bfloat16*)(smem + OFF_AS);
    float* sC = (float*)(smem + OFF_SC);
    int tid = threadIdx.x, w = tid >> 5, lane = tid & 31;
    int rowBase = blockIdx.x * 128;
    int rw = w >> 1, cw = w & 1;
    int ql = lane >> 2, qc = lane & 3;

    for (int i = tid; i < KCB; i += 256) sC[i] = g_C[i];
    for (int u = tid; u < 128 * 32; u += 256) {
        int r = u >> 5, c8 = u & 31;
        *(uint4*)(As + r * LDA + c8 * 8) =
            *(const uint4*)(g_xb + (size_t)(rowBase + r) * DIM + c8 * 8);
    }
    __syncthreads();

    unsigned asb = smem_u32(As);
    unsigned bsb = smem_u32(smem + OFF_BS);

    float Ar[4];
#pragma unroll
    for (int rs = 0; rs < 4; rs++)
        Ar[rs] = g_A[rowBase + rw * 32 + (rs >> 1) * 16 + (rs & 1) * 8 + ql];

    float tD[4][3]; int tI[4][3];
#pragma unroll
    for (int rs = 0; rs < 4; rs++)
#pragma unroll
        for (int s = 0; s < 3; s++) { tD[rs][s] = 3.4e38f; tI[rs][s] = 0x7ffffff0 + s; }

    int a_roff = ((lane >> 3) & 1) * 8 + (lane & 7);
    int a_koff = (lane >> 4) * 8;
    int b_noff = (lane >> 4) * 8 + (lane & 7);
    int b_koff = ((lane >> 3) & 1) * 8;

    // chunk0 of tile0
    prefetch_b(smem, tid, 0, 0, 0);

    for (int ct8 = 0; ct8 < 8; ct8++) {
        int ct = ct8 * 128;
        float acc[2][8][4];
#pragma unroll
        for (int mt = 0; mt < 2; mt++)
#pragma unroll
            for (int nt = 0; nt < 8; nt++)
#pragma unroll
                for (int v = 0; v < 4; v++) acc[mt][nt][v] = 0.f;

        for (int kc = 0; kc < 8; kc++) {
            if (kc + 1 < 8) { prefetch_b(smem, tid, (kc + 1) & 1, kc + 1, ct); CP_WAIT(1); }
            else            { CP_WAIT(0); }
            __syncthreads();
            unsigned bb = bsb + (kc & 1) * BS_BYTES;
#pragma unroll
            for (int ks = 0; ks < 2; ks++) {
                int kcol = kc * 32 + ks * 16;
                int bkcol = ks * 16;
                unsigned a[2][4];
#pragma unroll
                for (int mt = 0; mt < 2; mt++) {
                    unsigned addr = asb + ((rw * 32 + mt * 16 + a_roff) * LDA + kcol + a_koff) * 2;
                    LDSM4(a[mt][0], a[mt][1], a[mt][2], a[mt][3], addr);
                }
#pragma unroll
                for (int ng = 0; ng < 4; ng++) {
                    unsigned addr = bb + ((cw * 64 + ng * 16 + b_noff) * LDB + bkcol + b_koff) * 2;
                    unsigned b0, b1, b2, b3;
                    LDSM4(b0, b1, b2, b3, addr);
#pragma unroll
                    for (int mt = 0; mt < 2; mt++) {
                        mma16816(acc[mt][2 * ng],     a[mt], b0, b1);
                        mma16816(acc[mt][2 * ng + 1], a[mt], b2, b3);
                    }
                }
            }
            __syncthreads();
        }

        // hide next tile's first B load behind the epilogue (buf0 is free:
        // its last reader was kc=6's compute, fenced by kc=7's barriers)
        if (ct8 + 1 < 8) prefetch_b(smem, tid, 0, 0, ct + 128);

        // register epilogue: distances + threshold-filtered top-3
#pragma unroll
        for (int mt = 0; mt < 2; mt++)
#pragma unroll
            for (int nt = 0; nt < 8; nt++) {
                int cb = ct + cw * 64 + nt * 8 + qc * 2;
#pragma unroll
                for (int v = 0; v < 4; v++) {
                    int rs = mt * 2 + (v >> 1);
                    int code = cb + (v & 1);
                    float d = __fadd_rn(__fsub_rn(Ar[rs], __fmul_rn(2.0f, acc[mt][nt][v])),
                                        sC[code]);
                    if (d < tD[rs][2]) {
                        if (d < tD[rs][0]) {
                            tD[rs][2] = tD[rs][1]; tI[rs][2] = tI[rs][1];
                            tD[rs][1] = tD[rs][0]; tI[rs][1] = tI[rs][0];
                            tD[rs][0] = d; tI[rs][0] = code;
                        } else if (d < tD[rs][1]) {
                            tD[rs][2] = tD[rs][1]; tI[rs][2] = tI[rs][1];
                            tD[rs][1] = d; tI[rs][1] = code;
                        } else {
                            tD[rs][2] = d; tI[rs][2] = code;
                        }
                    }
                }
            }
    }

    // merge the 4 lanes (qc 0..3) sharing each row
#pragma unroll
    for (int rs = 0; rs < 4; rs++) {
#pragma unroll
        for (int step = 1; step <= 2; step++) {
            float md[6]; int mi[6];
#pragma unroll
            for (int s = 0; s < 3; s++) {
                md[s] = tD[rs][s]; mi[s] = tI[rs][s];
                md[3 + s] = __shfl_xor_sync(0xffffffffu, tD[rs][s], step);
                mi[3 + s] = __shfl_xor_sync(0xffffffffu, tI[rs][s], step);
            }
#pragma unroll
            for (int p = 0; p < 3; p++)
#pragma unroll
                for (int q = p + 1; q < 6; q++)
                    if (dless(md[q], mi[q], md[p], mi[p])) {
                        float td = md[p]; md[p] = md[q]; md[q] = td;
                        int   ti = mi[p]; mi[p] = mi[q]; mi[q] = ti;
                    }
#pragma unroll
            for (int s = 0; s < 3; s++) { tD[rs][s] = md[s]; tI[rs][s] = mi[s]; }
        }
    }

    float* mD = (float*)(smem + OFF_MG);
    int*   mI = (int*)(smem + OFF_MG + 128 * 2 * 3 * 4);
    if (qc == 0) {
#pragma unroll
        for (int rs = 0; rs < 4; rs++) {
            int rloc = rw * 32 + (rs >> 1) * 16 + (rs & 1) * 8 + ql;
#pragma unroll
            for (int s = 0; s < 3; s++) {
                mD[(rloc * 2 + cw) * 3 + s] = tD[rs][s];
                mI[(rloc * 2 + cw) * 3 + s] = tI[rs][s];
            }
        }
    }
    __syncthreads();
    if (tid < 128) {
        float md[6]; int mi[6];
#pragma unroll
        for (int s = 0; s < 3; s++) {
            md[s]     = mD[(tid * 2 + 0) * 3 + s]; mi[s]     = mI[(tid * 2 + 0) * 3 + s];
            md[3 + s] = mD[(tid * 2 + 1) * 3 + s]; mi[3 + s] = mI[(tid * 2 + 1) * 3 + s];
        }
#pragma unroll
        for (int p = 0; p < 3; p++)
#pragma unroll
            for (int q = p + 1; q < 6; q++)
                if (dless(md[q], mi[q], md[p], mi[p])) {
                    float td = md[p]; md[p] = md[q]; md[q] = td;
                    int   ti = mi[p]; mi[p] = mi[q]; mi[q] = ti;
                }
        int row = rowBase + tid;
#pragma unroll
        for (int s = 0; s < 3; s++) {
            g_cand[row * 3 + s] = mi[s];
            g_cd[row * 3 + s]   = md[s];
        }
    }
}

// ---------------- margin-gated exact rescore + fused histogram ----------------
#define MARGIN 1.5e-3f
__global__ __launch_bounds__(256) void k_rescore(const float* __restrict__ x,
                                                 const float* __restrict__ w) {
    int row = blockIdx.x * 256 + threadIdx.x;
    if (row >= NROWS) return;
    int c0 = g_cand[row * 3], c1 = g_cand[row * 3 + 1], c2 = g_cand[row * 3 + 2];
    float d0 = g_cd[row * 3], d1 = g_cd[row * 3 + 1];
    int bi;
    if (__fsub_rn(d1, d0) > MARGIN) {
        bi = c0;
    } else {
        int c[3] = { c0, c1, c2 };
        const float4* xr = (const float4*)(x + (size_t)row * DIM);
        const float4* wr[3];
#pragma unroll
        for (int s = 0; s < 3; s++) wr[s] = (const float4*)(w + (size_t)c[s] * DIM);
        float dot[3] = { 0.f, 0.f, 0.f };
#pragma unroll 4
        for (int k4 = 0; k4 < 64; k4++) {
            float4 xv = xr[k4];
#pragma unroll
            for (int s = 0; s < 3; s++) {
                float4 wv = wr[s][k4];
                dot[s] = __fmaf_rn(xv.x, wv.x, dot[s]);
                dot[s] = __fmaf_rn(xv.y, wv.y, dot[s]);
                dot[s] = __fmaf_rn(xv.z, wv.z, dot[s]);
                dot[s] = __fmaf_rn(xv.w, wv.w, dot[s]);
            }
        }
        float A = g_A[row];
        float bd = 3.4e38f; bi = 0x7fffffff;
#pragma unroll
        for (int s = 0; s < 3; s++) {
            float d = __fadd_rn(__fsub_rn(A, __fmul_rn(2.0f, dot[s])), g_C[c[s]]);
            if (dless(d, c[s], bd, bi)) { bd = d; bi = c[s]; }
        }
    }
    g_idx[row] = bi;
    atomicAdd(&g_ccount[bi], 1);
}

// ---- bucket pipeline: scan -> scatter -> dw gather ----
__global__ __launch_bounds__(1024) void k_scan() {
    __shared__ int sh[1024];
    int t = threadIdx.x;
    int v = g_ccount[t];
    sh[t] = v;
    __syncthreads();
    int sum = v;
    for (int o = 1; o < 1024; o <<= 1) {
        int add = (t >= o) ? sh[t - o] : 0;
        __syncthreads();
        sh[t] = sum = sum + add;
        __syncthreads();
    }
    g_off[t] = sum - v;
    g_counts[t] = (float)v;
}

__global__ __launch_bounds__(256) void k_scatter() {
    int i = blockIdx.x * 256 + threadIdx.x;
    if (i >= NROWS) return;
    int k = g_idx[i];
    int pos = atomicAdd(&g_cursor[k], 1);
    g_rows[g_off[k] + pos] = i;
}

__global__ __launch_bounds__(256) void k_dw(const float* __restrict__ x) {
    int k = blockIdx.x, d = threadIdx.x;
    int off = g_off[k], m = g_ccount[k];
    float a0 = 0.f, a1 = 0.f, a2 = 0.f, a3 = 0.f;
    int j = 0;
    for (; j + 3 < m; j += 4) {
        a0 += x[(size_t)g_rows[off + j] * DIM + d];
        a1 += x[(size_t)g_rows[off + j + 1] * DIM + d];
        a2 += x[(size_t)g_rows[off + j + 2] * DIM + d];
        a3 += x[(size_t)g_rows[off + j + 3] * DIM + d];
    }
    for (; j < m; j++) a0 += x[(size_t)g_rows[off + j] * DIM + d];
    g_dw[k * DIM + d] = (a0 + a1) + (a2 + a3);
}

// ---- gather codebook, STE output, loss partials (2x ILP) ----
__global__ __launch_bounds__(256) void k_quant(const float* __restrict__ x,
                                               const float* __restrict__ w,
                                               float* __restrict__ out) {
    __shared__ double sr[256];
    double ls = 0.0;
    const int half = NROWS * DIM / 8;
    int stride = gridDim.x * 256;
    for (int e4 = blockIdx.x * 256 + threadIdx.x; e4 < half; e4 += stride) {
        int eA = e4, eB = e4 + half;
        int rowA = eA >> 6, c4A = eA & 63;
        int rowB = eB >> 6, c4B = eB & 63;
        int kA = g_idx[rowA], kB = g_idx[rowB];
        float4 xA = ((const float4*)x)[eA];
        float4 xB = ((const float4*)x)[eB];
        float4 qA = ((const float4*)w)[kA * 64 + c4A];
        float4 qB = ((const float4*)w)[kB * 64 + c4B];
        float a0 = __fsub_rn(qA.x, xA.x), a1 = __fsub_rn(qA.y, xA.y);
        float a2 = __fsub_rn(qA.z, xA.z), a3 = __fsub_rn(qA.w, xA.w);
        float b0 = __fsub_rn(qB.x, xB.x), b1 = __fsub_rn(qB.y, xB.y);
        float b2 = __fsub_rn(qB.z, xB.z), b3 = __fsub_rn(qB.w, xB.w);
        float* oA = out + OFF_Q + (size_t)eA * 4;
        float* oB = out + OFF_Q + (size_t)eB * 4;
        oA[0] = __fadd_rn(xA.x, a0); oA[1] = __fadd_rn(xA.y, a1);
        oA[2] = __fadd_rn(xA.z, a2); oA[3] = __fadd_rn(xA.w, a3);
        oB[0] = __fadd_rn(xB.x, b0); oB[1] = __fadd_rn(xB.y, b1);
        oB[2] = __fadd_rn(xB.z, b2); oB[3] = __fadd_rn(xB.w, b3);
        float sA = __fmaf_rn(a0, a0, __fmaf_rn(a1, a1, __fmaf_rn(a2, a2, a3 * a3)));
        float sB = __fmaf_rn(b0, b0, __fmaf_rn(b1, b1, __fmaf_rn(b2, b2, b3 * b3)));
        ls += (double)sA + (double)sB;
    }
    sr[threadIdx.x] = ls;
    __syncthreads();
    for (int o = 128; o; o >>= 1) { if (threadIdx.x < o) sr[threadIdx.x] += sr[threadIdx.x + o]; __syncthreads(); }
    if (!threadIdx.x) g_lp[blockIdx.x] = sr[0];
}

// ---- scalars ----
__global__ __launch_bounds__(256) void k_scalars(const float* __restrict__ ecs,
                                                 float* __restrict__ out) {
    __shared__ double sd[256];
    int t = threadIdx.x;
    double s = 0;
    for (int i = t; i < 2048; i += 256) s += g_lp[i];
    sd[t] = s; __syncthreads();
    for (int o = 128; o; o >>= 1) { if (t < o) sd[t] += sd[t + o]; __syncthreads(); }
    double loss = 0.25 * sd[0] / ((double)NROWS * DIM);
    double ns = 0;
    for (int k = t; k < KCB; k += 256) {
        float ncs = __fadd_rn(__fmul_rn(0.99f, ecs[k]), __fmul_rn(0.01f, g_counts[k]));
        out[OFF_CS + k] = ncs;
        ns += ncs;
    }
    __syncthreads(); sd[t] = ns; __syncthreads();
    for (int o = 128; o; o >>= 1) { if (t < o) sd[t] += sd[t + o]; __syncthreads(); }
    float nf = (float)sd[0];
    float denom = __fadd_rn(nf, (float)(1024.0 * 1e-5));
    for (int k = t; k < KCB; k += 256) {
        float ncs = out[OFF_CS + k];
        g_cs[k] = __fmul_rn(__fdiv_rn(__fadd_rn(ncs, 1e-5f), denom), nf);
    }
    double ps = 0;
    for (int k = t; k < KCB; k += 256) {
        double p = (double)g_counts[k] / (double)NROWS;
        ps += p * log(p + 1e-10);
    }
    __syncthreads(); sd[t] = ps; __syncthreads();
    for (int o = 128; o; o >>= 1) { if (t < o) sd[t] += sd[t + o]; __syncthreads(); }
    if (!t) { out[OFF_LOSS] = (float)loss; out[OFF_PERP] = (float)exp(-sd[0]); }
}

// ---- EMA codebook update ----
__global__ __launch_bounds__(256) void k_emb(const float* __restrict__ emaw,
                                             float* __restrict__ out) {
    int e = blockIdx.x*256 + threadIdx.x;
    if (e >= KCB*DIM) return;
    int k = e >> 8;
    float ne = __fadd_rn(__fmul_rn(0.99f, emaw[e]), __fmul_rn(0.01f, g_dw[e]));
    out[OFF_EMA + e] = ne;
    out[OFF_EMB + e] = __fdiv_rn(ne, g_cs[k]);
}

extern "C" void kernel_launch(void* const* d_in, const int* in_sizes, int n_in,
                              void* d_out, int out_size) {
    const float* x    = (const float*)d_in[0];
    const float* w    = (const float*)d_in[1];
    const float* ecs  = (const float*)d_in[2];
    const float* emaw = (const float*)d_in[3];
    float* out = (float*)d_out;

    cudaFuncSetAttribute(k_mma_cand,
        cudaFuncAttributeMaxDynamicSharedMemorySize, SMEM_TOT);

    __nv_bfloat16 *xb, *wb;
    cudaGetSymbolAddress((void**)&xb, g_xb);
    cudaGetSymbolAddress((void**)&wb, g_wb);

    k_prep<<<NROWS/8, 256>>>(x, NROWS, 0, xb);       // 1
    k_prep<<<KCB/8,   256>>>(w, KCB,   1, wb);       // 2
    k_zero<<<4, 256>>>();                            // 3
    k_mma_cand<<<NROWS/128, 256, SMEM_TOT>>>();      // 4 <- profiled slot
    k_rescore<<<NROWS/256, 256>>>(x, w);             // 5
    k_scan<<<1, 1024>>>();                           // 6
    k_scatter<<<NROWS/256, 256>>>();                 // 7
    k_dw<<<KCB, 256>>>(x);                           // 8
    k_quant<<<2048, 256>>>(x, w, out);               // 9
    k_scalars<<<1, 256>>>(ecs, out);                 // 10
    k_emb<<<KCB*DIM/256, 256>>>(emaw, out);          // 11
}